// round 4
// baseline (speedup 1.0000x reference)
#include <cuda_runtime.h>
#include <cstdint>
#define B_ 32
#define C_ 128
#define P_ 4096
#define PI_ 3.14159265358979323846f

__device__ float  g_xc[B_*C_*P_];      // conv out; reused as LN-gated y
__device__ float  g_xl[B_*256*P_];     // gemm1 out: x_=m<128, z=m>=128
__device__ float  g_xo[B_*C_*P_];      // expert output
__device__ float2 g_cA[B_*C_*P_];      // complex scratch
__device__ float  g_we[C_*P_];
__device__ float  g_wn[4096];
__device__ float2 g_F64[4096];
__device__ float2 g_F128[16384];
__device__ float  g_meanx[B_*C_];
__device__ int    g_expert[B_];

__global__ void k_consts(){
  int i=blockIdx.x*256+threadIdx.x;
  if(i<4096){
    int n=i>>6,h=i&63;
    float v=cospif((float)n*(h+0.5f)/64.f)*sqrtf(2.f/64.f);
    if(n==0)v*=0.70710678118654752f;
    g_wn[i]=v;
    float a=(float)((n*h)&63)/32.f;
    g_F64[i]=make_float2(cospif(a),-sinpif(a));
  }
  if(i<16384){
    int k=i>>7,j=i&127;
    float a=(float)((k*j)&127)/64.f;
    g_F128[i]=make_float2(cospif(a),-sinpif(a));
  }
}

__global__ __launch_bounds__(256) void k_we(const float* __restrict__ fe,
    const float* __restrict__ tw,const float* __restrict__ tb){
  __shared__ float sfe[128*33];
  int t=threadIdx.x,p0=blockIdx.x*32;
  for(int idx=t;idx<4096;idx+=256){int pl=idx>>7,c=idx&127;sfe[c*33+pl]=fe[(p0+pl)*128+c];}
  __syncthreads();
  int pl=t&31,cg=t>>5,p=p0+pl,h=p>>6,w=p&63;
  float decay=expf(-(PI_*PI_/4096.f)*(float)(h*h+w*w));
  float acc[16];
  #pragma unroll
  for(int i=0;i<16;i++)acc[i]=0.f;
  for(int c2=0;c2<128;c2++){
    float f=sfe[c2*33+pl];
    #pragma unroll
    for(int i=0;i<16;i++)acc[i]+=f*__ldg(tw+(cg*16+i)*128+c2);
  }
  #pragma unroll
  for(int i=0;i<16;i++){
    int c=cg*16+i;
    float k=fmaxf(acc[i]+__ldg(tb+c),0.f);
    g_we[c*P_+p]=powf(decay,k);
  }
}

__global__ __launch_bounds__(256) void k_conv(const float* __restrict__ x,
    const float* __restrict__ wt,const float* __restrict__ bs){
  int b=blockIdx.z,c=blockIdx.y,p=blockIdx.x*256+threadIdx.x;
  int h=p>>6,w=p&63;
  const float* xp=x+(size_t)(b*C_+c)*P_;
  const float* wc=wt+c*9;
  float acc=__ldg(bs+c);
  #pragma unroll
  for(int dh=-1;dh<=1;dh++){
    int hh=h+dh; if(hh<0||hh>63)continue;
    #pragma unroll
    for(int dw=-1;dw<=1;dw++){
      int ww=w+dw; if(ww<0||ww>63)continue;
      acc+=xp[hh*64+ww]*__ldg(wc+(dh+1)*3+(dw+1));
    }
  }
  g_xc[(size_t)(b*C_+c)*P_+p]=acc;
}

__global__ __launch_bounds__(256) void k_gemm(const float* __restrict__ in,
    const float* __restrict__ W,const float* __restrict__ bias,
    float* __restrict__ out,int M){
  __shared__ float sA[16*65]; __shared__ float4 sB[256];
  int b=blockIdx.z,m0=blockIdx.y*64,p0=blockIdx.x*64,t=threadIdx.x;
  int tx=t&15,ty=t>>4;
  const float* X=in+(size_t)b*128*P_;
  float acc[4][4]={};
  for(int kt=0;kt<8;kt++){
    #pragma unroll
    for(int i=0;i<4;i++){int idx=t+i*256;sA[(idx&15)*65+(idx>>4)]=W[(m0+(idx>>4))*128+kt*16+(idx&15)];}
    sB[t]=*(const float4*)(X+(size_t)(kt*16+(t>>4))*P_+p0+(t&15)*4);
    __syncthreads();
    #pragma unroll
    for(int k=0;k<16;k++){
      float4 bv=sB[k*16+tx];
      #pragma unroll
      for(int i=0;i<4;i++){
        float a=sA[k*65+ty*4+i];
        acc[i][0]+=a*bv.x;acc[i][1]+=a*bv.y;acc[i][2]+=a*bv.z;acc[i][3]+=a*bv.w;
      }
    }
    __syncthreads();
  }
  #pragma unroll
  for(int i=0;i<4;i++){
    int m=m0+ty*4+i; float bb=__ldg(bias+m);
    *(float4*)(out+((size_t)b*M+m)*P_+p0+tx*4)=make_float4(acc[i][0]+bb,acc[i][1]+bb,acc[i][2]+bb,acc[i][3]+bb);
  }
}

__global__ void k_mean(){
  __shared__ float r[128];
  int c=blockIdx.x,b=blockIdx.y;
  const float* p=g_xl+(size_t)(b*256+c)*P_;
  float s=0.f;
  for(int i=threadIdx.x;i<P_;i+=128)s+=p[i];
  r[threadIdx.x]=s;__syncthreads();
  for(int st=64;st>0;st>>=1){if(threadIdx.x<st)r[threadIdx.x]+=r[threadIdx.x+st];__syncthreads();}
  if(threadIdx.x==0)g_meanx[b*128+c]=r[0]*(1.f/P_);
}

__global__ __launch_bounds__(256) void k_router(const float* p1w,const float* p1b,
    const float* g1,const float* b1,const float* p2w,const float* p2b,
    const float* g2,const float* b2,const float* p3w,const float* p3b,const float* gum){
  __shared__ float h1[8192],h2[1024];
  int t=threadIdx.x;
  for(int idx=t;idx<8192;idx+=256){
    int b=idx>>8,o=idx&255;float a=p1b[o];
    for(int c=0;c<128;c++)a+=g_meanx[b*128+c]*p1w[o*128+c];
    h1[idx]=a>0.f?a:0.1f*a;
  }
  __syncthreads();
  {int o=t;float s=0,s2=0;
   for(int b=0;b<32;b++){float v=h1[b*256+o];s+=v;s2+=v*v;}
   float mu=s/32.f,rs=rsqrtf(fmaxf(s2/32.f-mu*mu,0.f)+1e-5f);
   for(int b=0;b<32;b++)h1[b*256+o]=(h1[b*256+o]-mu)*rs*g1[o]+b1[o];}
  __syncthreads();
  for(int idx=t;idx<1024;idx+=256){
    int b=idx>>5,j=idx&31;float a=p2b[j];
    for(int o=0;o<256;o++)a+=h1[b*256+o]*p2w[j*256+o];
    h2[idx]=a>0.f?a:0.1f*a;
  }
  __syncthreads();
  if(t<32){int j=t;float s=0,s2=0;
   for(int b=0;b<32;b++){float v=h2[b*32+j];s+=v;s2+=v*v;}
   float mu=s/32.f,rs=rsqrtf(fmaxf(s2/32.f-mu*mu,0.f)+1e-5f);
   for(int b=0;b<32;b++)h2[b*32+j]=(h2[b*32+j]-mu)*rs*g2[j]+b2[j];}
  __syncthreads();
  if(t<32){int b=t;float best=-1e30f;int bi=0;
   for(int r=0;r<3;r++){
     float l=p3b[r]+gum[b*3+r];
     for(int j=0;j<32;j++)l+=h2[b*32+j]*p3w[r*32+j];
     if(l>best){best=l;bi=r;}
   }
   g_expert[b]=bi;}
}

// in-place row transform, output written transposed: sP[j][r] = sum_k M[r,k]*sP[k][j]
__device__ __forceinline__ void rmm(float* sP,const float* M,int tr,float sc){
  int j=threadIdx.x&63,g=threadIdx.x>>6;
  float a[16];
  #pragma unroll
  for(int i=0;i<16;i++)a[i]=0.f;
  for(int k=0;k<64;k++){
    float x=sP[k*65+j];
    #pragma unroll
    for(int i=0;i<16;i++){int r=g*16+i;a[i]+=x*__ldg(tr?&M[k*64+r]:&M[r*64+k]);}
  }
  __syncthreads();
  #pragma unroll
  for(int i=0;i<16;i++)sP[j*65+g*16+i]=a[i]*sc;
  __syncthreads();
}

__device__ __forceinline__ void cmm(float2* sP,const float2* M,int cj,float sc){
  int j=threadIdx.x&63,g=threadIdx.x>>6;
  float re[16],im[16];
  #pragma unroll
  for(int i=0;i<16;i++){re[i]=0.f;im[i]=0.f;}
  for(int k=0;k<64;k++){
    float2 x=sP[k*65+j];
    #pragma unroll
    for(int i=0;i<16;i++){
      float2 f=__ldg(&M[(g*16+i)*64+k]);
      float fy=cj?-f.y:f.y;
      re[i]+=f.x*x.x-fy*x.y;
      im[i]+=f.x*x.y+fy*x.x;
    }
  }
  __syncthreads();
  #pragma unroll
  for(int i=0;i<16;i++)sP[j*65+g*16+i]=make_float2(re[i]*sc,im[i]*sc);
  __syncthreads();
}

__global__ __launch_bounds__(256) void k_dct(){
  int c=blockIdx.x,b=blockIdx.y;
  if(g_expert[b]!=0)return;
  __shared__ float sP[64*65];
  int t=threadIdx.x;
  const float* src=g_xl+(size_t)(b*256+c)*P_;
  for(int idx=t;idx<4096;idx+=256)sP[(idx>>6)*65+(idx&63)]=src[idx];
  __syncthreads();
  rmm(sP,g_wn,0,1.f);       // T1^T[w][n]
  rmm(sP,g_wn,0,1.f);       // T2[n][m]
  for(int idx=t;idx<4096;idx+=256)sP[(idx>>6)*65+(idx&63)]*=__ldg(&g_we[c*P_+idx]);
  __syncthreads();
  rmm(sP,g_wn,1,1.f);       // T3^T[m][h]
  rmm(sP,g_wn,1,1.f);       // out[h][w]
  float* dst=g_xo+(size_t)(b*C_+c)*P_;
  for(int idx=t;idx<4096;idx+=256)dst[idx]=sP[(idx>>6)*65+(idx&63)];
}

__global__ __launch_bounds__(256) void k_Cf(){
  int b=blockIdx.y;
  if(g_expert[b]!=1)return;
  __shared__ float2 sF[2048]; __shared__ float sX[512];
  int t=threadIdx.x,pl=t&31,cg=t>>5,p0=blockIdx.x*32;
  const float* Xb=g_xl+(size_t)b*256*P_;
  float re[16],im[16];
  #pragma unroll
  for(int i=0;i<16;i++){re[i]=0.f;im[i]=0.f;}
  for(int kt=0;kt<8;kt++){
    #pragma unroll
    for(int i=0;i<8;i++){int idx=t+i*256;sF[idx]=g_F128[(idx>>4)*128+kt*16+(idx&15)];}
    #pragma unroll
    for(int i=0;i<2;i++){int idx=t+i*256;sX[idx]=Xb[(size_t)(kt*16+(idx>>5))*P_+p0+(idx&31)];}
    __syncthreads();
    #pragma unroll
    for(int k=0;k<16;k++){
      float xv=sX[k*32+pl];
      #pragma unroll
      for(int i=0;i<16;i++){
        float2 f=sF[(cg+8*i)*16+k];
        re[i]+=f.x*xv;im[i]+=f.y*xv;
      }
    }
    __syncthreads();
  }
  #pragma unroll
  for(int i=0;i<16;i++)g_cA[(size_t)(b*C_+cg+8*i)*P_+p0+pl]=make_float2(re[i],im[i]);
}

__global__ __launch_bounds__(256) void k_plane(){
  int c=blockIdx.x,b=blockIdx.y;
  if(g_expert[b]!=1)return;
  __shared__ float2 sP[64*65];
  int t=threadIdx.x;
  float2* src=g_cA+(size_t)(b*C_+c)*P_;
  for(int idx=t;idx<4096;idx+=256)sP[(idx>>6)*65+(idx&63)]=src[idx];
  __syncthreads();
  cmm(sP,g_F64,0,1.f);
  cmm(sP,g_F64,0,1.f);
  for(int idx=t;idx<4096;idx+=256){
    float w=__ldg(&g_we[c*P_+idx]);
    float2 v=sP[(idx>>6)*65+(idx&63)];
    sP[(idx>>6)*65+(idx&63)]=make_float2(v.x*w,v.y*w);
  }
  __syncthreads();
  cmm(sP,g_F64,1,1.f/64.f);
  cmm(sP,g_F64,1,1.f/64.f);
  for(int idx=t;idx<4096;idx+=256)src[idx]=sP[(idx>>6)*65+(idx&63)];
}

__global__ __launch_bounds__(256) void k_Ci(){
  int b=blockIdx.y;
  if(g_expert[b]!=1)return;
  __shared__ float2 sF[2048]; __shared__ float2 sX[512];
  int t=threadIdx.x,pl=t&31,cg=t>>5,p0=blockIdx.x*32;
  float acc[16];
  #pragma unroll
  for(int i=0;i<16;i++)acc[i]=0.f;
  for(int kt=0;kt<8;kt++){
    #pragma unroll
    for(int i=0;i<8;i++){int idx=t+i*256;sF[idx]=g_F128[(idx>>4)*128+kt*16+(idx&15)];}
    #pragma unroll
    for(int i=0;i<2;i++){int idx=t+i*256;sX[idx]=g_cA[(size_t)(b*C_+kt*16+(idx>>5))*P_+p0+(idx&31)];}
    __syncthreads();
    #pragma unroll
    for(int k=0;k<16;k++){
      float2 xv=sX[k*32+pl];
      #pragma unroll
      for(int i=0;i<16;i++){
        float2 f=sF[(cg+8*i)*16+k];
        acc[i]+=f.x*xv.x+f.y*xv.y;   // Re(conj(F)*X)
      }
    }
    __syncthreads();
  }
  #pragma unroll
  for(int i=0;i<16;i++)g_xo[(size_t)(b*C_+cg+8*i)*P_+p0+pl]=acc[i]*(1.f/128.f);
}

__global__ __launch_bounds__(256) void k_haar(){
  int b=blockIdx.y;
  if(g_expert[b]!=2)return;
  int gid=blockIdx.x*256+threadIdx.x;     // 131072 quads
  int cp=gid>>11,q=gid&2047,h=q>>5,wp=q&31;
  size_t i0=(size_t)(b*256+2*cp)*P_+h*64+2*wp;
  float2 t0=*(const float2*)(g_xl+i0);
  float2 t1=*(const float2*)(g_xl+i0+P_);
  float sab=t0.x+t0.y,dab=t0.x-t0.y,scd=t1.x+t1.y,dcd=t1.x-t1.y;
  int pa=h*64+wp,pd=h*64+32+wp;
  float u00=(sab+scd)*0.25f*__ldg(&g_we[cp*P_+pa]);
  float u10=(sab-scd)*0.25f*__ldg(&g_we[(64+cp)*P_+pa]);
  float u01=(dab+dcd)*0.25f*__ldg(&g_we[cp*P_+pd]);
  float u11=(dab-dcd)*0.25f*__ldg(&g_we[(64+cp)*P_+pd]);
  float r0=u00+u01,r1=u00-u01,s0=u10+u11,s1=u10-u11;
  size_t o0=(size_t)(b*C_+2*cp)*P_+h*64+2*wp;
  *(float2*)(g_xo+o0)=make_float2(r0+s0,r1+s1);
  *(float2*)(g_xo+o0+P_)=make_float2(r0-s0,r1-s1);
}

__global__ __launch_bounds__(256) void k_lng(const float* __restrict__ og,
    const float* __restrict__ ob){
  int b=blockIdx.y,p=blockIdx.x*256+threadIdx.x;
  float s=0.f,s2=0.f;
  for(int c=0;c<128;c++){float v=g_xo[(size_t)(b*C_+c)*P_+p];s+=v;s2+=v*v;}
  float mu=s*(1.f/128.f);
  float rs=rsqrtf(fmaxf(s2*(1.f/128.f)-mu*mu,0.f)+1e-5f);
  for(int c=0;c<128;c++){
    float v=g_xo[(size_t)(b*C_+c)*P_+p];
    float z=g_xl[(size_t)(b*256+128+c)*P_+p];
    float sil=z/(1.f+expf(-z));
    g_xc[(size_t)(b*C_+c)*P_+p]=((v-mu)*rs*__ldg(og+c)+__ldg(ob+c))*sil;
  }
}

extern "C" void kernel_launch(void* const* d_in,const int* in_sizes,int n_in,
                              void* d_out,int out_size){
  const float* x=(const float*)d_in[0];
  const float* fe=(const float*)d_in[1];
  const float* dww=(const float*)d_in[2];
  const float* dwb=(const float*)d_in[3];
  const float* lw=(const float*)d_in[4];
  const float* lb=(const float*)d_in[5];
  const float* p1w=(const float*)d_in[6];
  const float* p1b=(const float*)d_in[7];
  const float* g1=(const float*)d_in[8];
  const float* b1=(const float*)d_in[9];
  const float* p2w=(const float*)d_in[10];
  const float* p2b=(const float*)d_in[11];
  const float* g2=(const float*)d_in[12];
  const float* b2=(const float*)d_in[13];
  const float* p3w=(const float*)d_in[14];
  const float* p3b=(const float*)d_in[15];
  const float* tw=(const float*)d_in[16];
  const float* tb=(const float*)d_in[17];
  const float* og=(const float*)d_in[18];
  const float* ob=(const float*)d_in[19];
  const float* olw=(const float*)d_in[20];
  const float* olb=(const float*)d_in[21];
  const float* gum=(const float*)d_in[22];
  float* out=(float*)d_out;
  float* gxc; cudaGetSymbolAddress((void**)&gxc,g_xc);
  float* gxl; cudaGetSymbolAddress((void**)&gxl,g_xl);

  k_consts<<<64,256>>>();
  k_we<<<128,256>>>(fe,tw,tb);
  k_conv<<<dim3(16,128,32),256>>>(x,dww,dwb);
  k_gemm<<<dim3(64,4,32),256>>>(gxc,lw,lb,gxl,256);
  k_mean<<<dim3(128,32),128>>>();
  k_router<<<1,256>>>(p1w,p1b,g1,b1,p2w,p2b,g2,b2,p3w,p3b,gum);
  k_dct<<<dim3(128,32),256>>>();
  k_Cf<<<dim3(128,32),256>>>();
  k_plane<<<dim3(128,32),256>>>();
  k_Ci<<<dim3(128,32),256>>>();
  k_haar<<<dim3(512,32),256>>>();
  k_lng<<<dim3(16,32),256>>>(og,ob);
  k_gemm<<<dim3(64,2,32),256>>>(gxc,olw,olb,out,128);
}

// round 5
// speedup vs baseline: 1.2507x; 1.2507x over previous
#include <cuda_runtime.h>
#include <cstdint>
#define B_ 32
#define C_ 128
#define P_ 4096
#define PI_ 3.14159265358979323846f

__device__ float  g_xc[B_*C_*P_];
__device__ float  g_xl[B_*256*P_];
__device__ float  g_xo[B_*C_*P_];
__device__ float2 g_cA[B_*C_*P_];
__device__ float  g_we[C_*P_];
__device__ float  g_wn[4096];
__device__ float2 g_F64[4096];
__device__ float2 g_F128[16384];
__device__ float  g_meanx[B_*C_];
__device__ int    g_expert[B_];

__global__ void k_consts(){
  int i=blockIdx.x*256+threadIdx.x;
  if(i<4096){
    int n=i>>6,h=i&63;
    float v=cospif((float)n*(h+0.5f)/64.f)*sqrtf(2.f/64.f);
    if(n==0)v*=0.70710678118654752f;
    g_wn[i]=v;
    float a=(float)((n*h)&63)/32.f;
    g_F64[i]=make_float2(cospif(a),-sinpif(a));
  }
  if(i<16384){
    int k=i>>7,j=i&127;
    float a=(float)((k*j)&127)/64.f;
    g_F128[i]=make_float2(cospif(a),-sinpif(a));
  }
}

__global__ __launch_bounds__(256) void k_we(const float* __restrict__ fe,
    const float* __restrict__ tw,const float* __restrict__ tb){
  __shared__ float sfe[128*33];
  int t=threadIdx.x,p0=blockIdx.x*32;
  for(int idx=t;idx<4096;idx+=256){int pl=idx>>7,c=idx&127;sfe[c*33+pl]=fe[(p0+pl)*128+c];}
  __syncthreads();
  int pl=t&31,cg=t>>5,p=p0+pl,h=p>>6,w=p&63;
  float s=(PI_*PI_/4096.f)*(float)(h*h+w*w);
  float acc[16];
  #pragma unroll
  for(int i=0;i<16;i++)acc[i]=0.f;
  for(int c2=0;c2<128;c2++){
    float f=sfe[c2*33+pl];
    #pragma unroll
    for(int i=0;i<16;i++)acc[i]+=f*__ldg(tw+(cg*16+i)*128+c2);
  }
  #pragma unroll
  for(int i=0;i<16;i++){
    int c=cg*16+i;
    float k=fmaxf(acc[i]+__ldg(tb+c),0.f);
    g_we[c*P_+p]=expf(-s*k);
  }
}

__global__ __launch_bounds__(256) void k_conv(const float* __restrict__ x,
    const float* __restrict__ wt,const float* __restrict__ bs){
  int b=blockIdx.z,c=blockIdx.y,p=blockIdx.x*256+threadIdx.x;
  int h=p>>6,w=p&63;
  const float* xp=x+(size_t)(b*C_+c)*P_;
  const float* wc=wt+c*9;
  float acc=__ldg(bs+c);
  #pragma unroll
  for(int dh=-1;dh<=1;dh++){
    int hh=h+dh; if(hh<0||hh>63)continue;
    #pragma unroll
    for(int dw=-1;dw<=1;dw++){
      int ww=w+dw; if(ww<0||ww>63)continue;
      acc+=xp[hh*64+ww]*__ldg(wc+(dh+1)*3+(dw+1));
    }
  }
  g_xc[(size_t)(b*C_+c)*P_+p]=acc;
}

__global__ __launch_bounds__(256) void k_gemm(const float* __restrict__ in,
    const float* __restrict__ W,const float* __restrict__ bias,
    float* __restrict__ out,int M){
  __shared__ float sA[16*65]; __shared__ float4 sB[256];
  int b=blockIdx.z,m0=blockIdx.y*64,p0=blockIdx.x*64,t=threadIdx.x;
  int tx=t&15,ty=t>>4;
  const float* X=in+(size_t)b*128*P_;
  float acc[4][4]={};
  for(int kt=0;kt<8;kt++){
    #pragma unroll
    for(int i=0;i<4;i++){int idx=t+i*256;sA[(idx&15)*65+(idx>>4)]=W[(m0+(idx>>4))*128+kt*16+(idx&15)];}
    sB[t]=*(const float4*)(X+(size_t)(kt*16+(t>>4))*P_+p0+(t&15)*4);
    __syncthreads();
    #pragma unroll
    for(int k=0;k<16;k++){
      float4 bv=sB[k*16+tx];
      #pragma unroll
      for(int i=0;i<4;i++){
        float a=sA[k*65+ty*4+i];
        acc[i][0]+=a*bv.x;acc[i][1]+=a*bv.y;acc[i][2]+=a*bv.z;acc[i][3]+=a*bv.w;
      }
    }
    __syncthreads();
  }
  #pragma unroll
  for(int i=0;i<4;i++){
    int m=m0+ty*4+i; float bb=__ldg(bias+m);
    *(float4*)(out+((size_t)b*M+m)*P_+p0+tx*4)=make_float4(acc[i][0]+bb,acc[i][1]+bb,acc[i][2]+bb,acc[i][3]+bb);
  }
}

__global__ void k_mean(){
  __shared__ float r[128];
  int c=blockIdx.x,b=blockIdx.y;
  const float* p=g_xl+(size_t)(b*256+c)*P_;
  float s=0.f;
  for(int i=threadIdx.x;i<P_;i+=128)s+=p[i];
  r[threadIdx.x]=s;__syncthreads();
  for(int st=64;st>0;st>>=1){if(threadIdx.x<st)r[threadIdx.x]+=r[threadIdx.x+st];__syncthreads();}
  if(threadIdx.x==0)g_meanx[b*128+c]=r[0]*(1.f/P_);
}

__global__ __launch_bounds__(256) void k_router(const float* p1w,const float* p1b,
    const float* g1,const float* b1,const float* p2w,const float* p2b,
    const float* g2,const float* b2,const float* p3w,const float* p3b,const float* gum){
  __shared__ float h1[8192],h2[1024];
  int t=threadIdx.x;
  for(int idx=t;idx<8192;idx+=256){
    int b=idx>>8,o=idx&255;float a=p1b[o];
    for(int c=0;c<128;c++)a+=g_meanx[b*128+c]*p1w[o*128+c];
    h1[idx]=a>0.f?a:0.1f*a;
  }
  __syncthreads();
  {int o=t;float s=0,s2=0;
   for(int b=0;b<32;b++){float v=h1[b*256+o];s+=v;s2+=v*v;}
   float mu=s/32.f,rs=rsqrtf(fmaxf(s2/32.f-mu*mu,0.f)+1e-5f);
   for(int b=0;b<32;b++)h1[b*256+o]=(h1[b*256+o]-mu)*rs*g1[o]+b1[o];}
  __syncthreads();
  for(int idx=t;idx<1024;idx+=256){
    int b=idx>>5,j=idx&31;float a=p2b[j];
    for(int o=0;o<256;o++)a+=h1[b*256+o]*p2w[j*256+o];
    h2[idx]=a>0.f?a:0.1f*a;
  }
  __syncthreads();
  if(t<32){int j=t;float s=0,s2=0;
   for(int b=0;b<32;b++){float v=h2[b*32+j];s+=v;s2+=v*v;}
   float mu=s/32.f,rs=rsqrtf(fmaxf(s2/32.f-mu*mu,0.f)+1e-5f);
   for(int b=0;b<32;b++)h2[b*32+j]=(h2[b*32+j]-mu)*rs*g2[j]+b2[j];}
  __syncthreads();
  if(t<32){int b=t;float best=-1e30f;int bi=0;
   for(int r=0;r<3;r++){
     float l=p3b[r]+gum[b*3+r];
     for(int j=0;j<32;j++)l+=h2[b*32+j]*p3w[r*32+j];
     if(l>best){best=l;bi=r;}
   }
   g_expert[b]=bi;}
}

__device__ __forceinline__ void rmm(float* sP,const float* M,int tr,float sc){
  int j=threadIdx.x&63,g=threadIdx.x>>6;
  float a[16];
  #pragma unroll
  for(int i=0;i<16;i++)a[i]=0.f;
  for(int k=0;k<64;k++){
    float x=sP[k*65+j];
    #pragma unroll
    for(int i=0;i<16;i++){int r=g*16+i;a[i]+=x*(tr?M[k*64+r]:M[r*64+k]);}
  }
  __syncthreads();
  #pragma unroll
  for(int i=0;i<16;i++)sP[j*65+g*16+i]=a[i]*sc;
  __syncthreads();
}

__global__ __launch_bounds__(256) void k_dct(){
  int c=blockIdx.x,b=blockIdx.y;
  if(g_expert[b]!=0)return;
  __shared__ float sP[64*65]; __shared__ float sM[4096];
  int t=threadIdx.x;
  const float* src=g_xl+(size_t)(b*256+c)*P_;
  for(int idx=t;idx<4096;idx+=256){sM[idx]=g_wn[idx];sP[(idx>>6)*65+(idx&63)]=src[idx];}
  __syncthreads();
  rmm(sP,sM,0,1.f);
  rmm(sP,sM,0,1.f);
  for(int idx=t;idx<4096;idx+=256)sP[(idx>>6)*65+(idx&63)]*=__ldg(&g_we[c*P_+idx]);
  __syncthreads();
  rmm(sP,sM,1,1.f);
  rmm(sP,sM,1,1.f);
  float* dst=g_xo+(size_t)(b*C_+c)*P_;
  for(int idx=t;idx<4096;idx+=256)dst[idx]=sP[(idx>>6)*65+(idx&63)];
}

// ---------------- radix-8 FFT machinery ----------------
__device__ __forceinline__ float2 cmul(float2 a,float2 b){return make_float2(a.x*b.x-a.y*b.y,a.x*b.y+a.y*b.x);}
__device__ __forceinline__ float2 cmulc(float2 a,float2 b){return make_float2(a.x*b.x+a.y*b.y,a.y*b.x-a.x*b.y);}
__device__ __forceinline__ float2 cadd(float2 a,float2 b){return make_float2(a.x+b.x,a.y+b.y);}
__device__ __forceinline__ float2 csub(float2 a,float2 b){return make_float2(a.x-b.x,a.y-b.y);}

// 8-pt DFT, natural in, natural out. s=-1 fwd (w=e^{-2pi i/8}), s=+1 inv (unnormalized)
__device__ __forceinline__ void fft8(float2* a,float s){
  const float c8=0.70710678118654752f;
  float2 w1=make_float2(c8,s*c8),w2=make_float2(0.f,s),w3=make_float2(-c8,s*c8),t;
  t=csub(a[0],a[4]);a[0]=cadd(a[0],a[4]);a[4]=t;
  t=csub(a[1],a[5]);a[1]=cadd(a[1],a[5]);a[5]=cmul(t,w1);
  t=csub(a[2],a[6]);a[2]=cadd(a[2],a[6]);a[6]=cmul(t,w2);
  t=csub(a[3],a[7]);a[3]=cadd(a[3],a[7]);a[7]=cmul(t,w3);
  t=csub(a[0],a[2]);a[0]=cadd(a[0],a[2]);a[2]=t;
  t=csub(a[1],a[3]);a[1]=cadd(a[1],a[3]);a[3]=cmul(t,w2);
  t=csub(a[4],a[6]);a[4]=cadd(a[4],a[6]);a[6]=t;
  t=csub(a[5],a[7]);a[5]=cadd(a[5],a[7]);a[7]=cmul(t,w2);
  t=csub(a[0],a[1]);a[0]=cadd(a[0],a[1]);a[1]=t;
  t=csub(a[2],a[3]);a[2]=cadd(a[2],a[3]);a[3]=t;
  t=csub(a[4],a[5]);a[4]=cadd(a[4],a[5]);a[5]=t;
  t=csub(a[6],a[7]);a[6]=cadd(a[6],a[7]);a[7]=t;
  t=a[1];a[1]=a[4];a[4]=t;
  t=a[3];a[3]=a[6];a[6]=t;
}

// 64-pt FFT along one axis of a 64x64 tile (row stride 65 float2).
// Forward: natural in -> digit8-swapped out. Inverse: digit8-swapped in -> natural out.
// es: element stride, vs: vector stride. All 64 vectors, 256 threads.
__device__ void fft64_dir(float2* sP,int es,int vs,float sgn,bool inverse){
  int t=threadIdx.x,v=t&63,sl=t>>6;
  #pragma unroll
  for(int gi=0;gi<2;gi++){
    int g=sl+gi*4;
    float2 a[8];
    if(!inverse){
      #pragma unroll
      for(int n1=0;n1<8;n1++)a[n1]=sP[(8*n1+g)*es+v*vs];
      fft8(a,sgn);
      #pragma unroll
      for(int k1=1;k1<8;k1++)a[k1]=cmul(a[k1],__ldg(&g_F64[g*64+k1]));
      #pragma unroll
      for(int k1=0;k1<8;k1++)sP[(8*k1+g)*es+v*vs]=a[k1];
    }else{
      #pragma unroll
      for(int k2=0;k2<8;k2++)a[k2]=sP[(8*g+k2)*es+v*vs];
      fft8(a,sgn);
      #pragma unroll
      for(int n2=1;n2<8;n2++)a[n2]=cmulc(a[n2],__ldg(&g_F64[n2*64+g]));
      #pragma unroll
      for(int n2=0;n2<8;n2++)sP[(8*g+n2)*es+v*vs]=a[n2];
    }
  }
  __syncthreads();
  #pragma unroll
  for(int gi=0;gi<2;gi++){
    int g=sl+gi*4;
    float2 a[8];
    if(!inverse){
      #pragma unroll
      for(int n2=0;n2<8;n2++)a[n2]=sP[(8*g+n2)*es+v*vs];
      fft8(a,sgn);
      #pragma unroll
      for(int k2=0;k2<8;k2++)sP[(8*g+k2)*es+v*vs]=a[k2];
    }else{
      #pragma unroll
      for(int k1=0;k1<8;k1++)a[k1]=sP[(8*k1+g)*es+v*vs];
      fft8(a,sgn);
      #pragma unroll
      for(int n1=0;n1<8;n1++)sP[(8*n1+g)*es+v*vs]=a[n1];
    }
  }
  __syncthreads();
}

__global__ __launch_bounds__(256) void k_Cf(){
  int b=blockIdx.y;
  if(g_expert[b]!=1)return;
  __shared__ float2 sF[2048]; __shared__ float sX[512];
  int t=threadIdx.x,pl=t&31,cg=t>>5,p0=blockIdx.x*32;
  const float* Xb=g_xl+(size_t)b*256*P_;
  float re[16],im[16];
  #pragma unroll
  for(int i=0;i<16;i++){re[i]=0.f;im[i]=0.f;}
  for(int kt=0;kt<8;kt++){
    #pragma unroll
    for(int i=0;i<8;i++){int idx=t+i*256;sF[idx]=g_F128[(idx>>4)*128+kt*16+(idx&15)];}
    #pragma unroll
    for(int i=0;i<2;i++){int idx=t+i*256;sX[idx]=Xb[(size_t)(kt*16+(idx>>5))*P_+p0+(idx&31)];}
    __syncthreads();
    #pragma unroll
    for(int k=0;k<16;k++){
      float xv=sX[k*32+pl];
      #pragma unroll
      for(int i=0;i<16;i++){
        float2 f=sF[(cg+8*i)*16+k];
        re[i]+=f.x*xv;im[i]+=f.y*xv;
      }
    }
    __syncthreads();
  }
  #pragma unroll
  for(int i=0;i<16;i++)g_cA[(size_t)(b*C_+cg+8*i)*P_+p0+pl]=make_float2(re[i],im[i]);
}

// fused plane filter: fwd 2D FFT, we-multiply (digit-swapped index), inv 2D FFT
__global__ __launch_bounds__(256) void k_pfft(){
  int c=blockIdx.x,b=blockIdx.y;
  if(g_expert[b]!=1)return;
  __shared__ float2 sP[64*65];
  int t=threadIdx.x;
  float2* src=g_cA+(size_t)(b*C_+c)*P_;
  for(int idx=t;idx<4096;idx+=256)sP[(idx>>6)*65+(idx&63)]=src[idx];
  __syncthreads();
  fft64_dir(sP,65,1,-1.f,false);   // H forward
  fft64_dir(sP,1,65,-1.f,false);   // W forward
  for(int idx=t;idx<4096;idx+=256){
    int ph=idx>>6,pw=idx&63;
    int f=(((ph&7)<<3)|(ph>>3))*64+(((pw&7)<<3)|(pw>>3));
    float w=__ldg(&g_we[c*P_+f])*(1.f/4096.f);
    float2 v=sP[ph*65+pw];
    sP[ph*65+pw]=make_float2(v.x*w,v.y*w);
  }
  __syncthreads();
  fft64_dir(sP,1,65,1.f,true);     // W inverse
  fft64_dir(sP,65,1,1.f,true);     // H inverse
  for(int idx=t;idx<4096;idx+=256)src[idx]=sP[(idx>>6)*65+(idx&63)];
}

__global__ __launch_bounds__(256) void k_Ci(){
  int b=blockIdx.y;
  if(g_expert[b]!=1)return;
  __shared__ float2 sF[2048]; __shared__ float2 sX[512];
  int t=threadIdx.x,pl=t&31,cg=t>>5,p0=blockIdx.x*32;
  float acc[16];
  #pragma unroll
  for(int i=0;i<16;i++)acc[i]=0.f;
  for(int kt=0;kt<8;kt++){
    #pragma unroll
    for(int i=0;i<8;i++){int idx=t+i*256;sF[idx]=g_F128[(idx>>4)*128+kt*16+(idx&15)];}
    #pragma unroll
    for(int i=0;i<2;i++){int idx=t+i*256;sX[idx]=g_cA[(size_t)(b*C_+kt*16+(idx>>5))*P_+p0+(idx&31)];}
    __syncthreads();
    #pragma unroll
    for(int k=0;k<16;k++){
      float2 xv=sX[k*32+pl];
      #pragma unroll
      for(int i=0;i<16;i++){
        float2 f=sF[(cg+8*i)*16+k];
        acc[i]+=f.x*xv.x+f.y*xv.y;
      }
    }
    __syncthreads();
  }
  #pragma unroll
  for(int i=0;i<16;i++)g_xo[(size_t)(b*C_+cg+8*i)*P_+p0+pl]=acc[i]*(1.f/128.f);
}

__global__ __launch_bounds__(256) void k_haar(){
  int b=blockIdx.y;
  if(g_expert[b]!=2)return;
  int gid=blockIdx.x*256+threadIdx.x;
  int cp=gid>>11,q=gid&2047,h=q>>5,wp=q&31;
  size_t i0=(size_t)(b*256+2*cp)*P_+h*64+2*wp;
  float2 t0=*(const float2*)(g_xl+i0);
  float2 t1=*(const float2*)(g_xl+i0+P_);
  float sab=t0.x+t0.y,dab=t0.x-t0.y,scd=t1.x+t1.y,dcd=t1.x-t1.y;
  int pa=h*64+wp,pd=h*64+32+wp;
  float u00=(sab+scd)*0.25f*__ldg(&g_we[cp*P_+pa]);
  float u10=(sab-scd)*0.25f*__ldg(&g_we[(64+cp)*P_+pa]);
  float u01=(dab+dcd)*0.25f*__ldg(&g_we[cp*P_+pd]);
  float u11=(dab-dcd)*0.25f*__ldg(&g_we[(64+cp)*P_+pd]);
  float r0=u00+u01,r1=u00-u01,s0=u10+u11,s1=u10-u11;
  size_t o0=(size_t)(b*C_+2*cp)*P_+h*64+2*wp;
  *(float2*)(g_xo+o0)=make_float2(r0+s0,r1+s1);
  *(float2*)(g_xo+o0+P_)=make_float2(r0-s0,r1-s1);
}

__global__ __launch_bounds__(256) void k_lng(const float* __restrict__ og,
    const float* __restrict__ ob){
  int b=blockIdx.y,p=blockIdx.x*256+threadIdx.x;
  float s=0.f,s2=0.f;
  for(int c=0;c<128;c++){float v=g_xo[(size_t)(b*C_+c)*P_+p];s+=v;s2+=v*v;}
  float mu=s*(1.f/128.f);
  float rs=rsqrtf(fmaxf(s2*(1.f/128.f)-mu*mu,0.f)+1e-5f);
  for(int c=0;c<128;c++){
    float v=g_xo[(size_t)(b*C_+c)*P_+p];
    float z=g_xl[(size_t)(b*256+128+c)*P_+p];
    float sil=z/(1.f+expf(-z));
    g_xc[(size_t)(b*C_+c)*P_+p]=((v-mu)*rs*__ldg(og+c)+__ldg(ob+c))*sil;
  }
}

extern "C" void kernel_launch(void* const* d_in,const int* in_sizes,int n_in,
                              void* d_out,int out_size){
  const float* x=(const float*)d_in[0];
  const float* fe=(const float*)d_in[1];
  const float* dww=(const float*)d_in[2];
  const float* dwb=(const float*)d_in[3];
  const float* lw=(const float*)d_in[4];
  const float* lb=(const float*)d_in[5];
  const float* p1w=(const float*)d_in[6];
  const float* p1b=(const float*)d_in[7];
  const float* g1=(const float*)d_in[8];
  const float* b1=(const float*)d_in[9];
  const float* p2w=(const float*)d_in[10];
  const float* p2b=(const float*)d_in[11];
  const float* g2=(const float*)d_in[12];
  const float* b2=(const float*)d_in[13];
  const float* p3w=(const float*)d_in[14];
  const float* p3b=(const float*)d_in[15];
  const float* tw=(const float*)d_in[16];
  const float* tb=(const float*)d_in[17];
  const float* og=(const float*)d_in[18];
  const float* ob=(const float*)d_in[19];
  const float* olw=(const float*)d_in[20];
  const float* olb=(const float*)d_in[21];
  const float* gum=(const float*)d_in[22];
  float* out=(float*)d_out;
  float* gxc; cudaGetSymbolAddress((void**)&gxc,g_xc);
  float* gxl; cudaGetSymbolAddress((void**)&gxl,g_xl);

  k_consts<<<64,256>>>();
  k_we<<<128,256>>>(fe,tw,tb);
  k_conv<<<dim3(16,128,32),256>>>(x,dww,dwb);
  k_gemm<<<dim3(64,4,32),256>>>(gxc,lw,lb,gxl,256);
  k_mean<<<dim3(128,32),128>>>();
  k_router<<<1,256>>>(p1w,p1b,g1,b1,p2w,p2b,g2,b2,p3w,p3b,gum);
  k_dct<<<dim3(128,32),256>>>();
  k_Cf<<<dim3(128,32),256>>>();
  k_pfft<<<dim3(128,32),256>>>();
  k_Ci<<<dim3(128,32),256>>>();
  k_haar<<<dim3(512,32),256>>>();
  k_lng<<<dim3(16,32),256>>>(og,ob);
  k_gemm<<<dim3(64,2,32),256>>>(gxc,olw,olb,out,128);
}